// round 6
// baseline (speedup 1.0000x reference)
#include <cuda_runtime.h>
#include <math.h>
#include <stdint.h>

#define B   8
#define H   16
#define HD  128
#define D   2048
#define NB  512
#define BS  64
#define MB  64
#define KV  (MB*BS)        // 4096
#define NCHUNK 16
#define CHUNK  (KV/NCHUNK) // 256

// ---------------- scratch (no allocations allowed) ----------------
__device__ float g_q[B*D];
__device__ float g_k[B*D];
__device__ float g_v[B*D];
__device__ float g_o[B*D];
__device__ float g_pm[B*H*NCHUNK];
__device__ float g_pl[B*H*NCHUNK];
__device__ float g_po[B*H*NCHUNK*HD];

__device__ __forceinline__ float warp_sum(float v) {
#pragma unroll
    for (int o = 16; o; o >>= 1) v += __shfl_xor_sync(0xffffffffu, v, o);
    return v;
}

// ---------------- tiled GEMV: 16 columns per block, X staged in smem ----------
template<int WHICH_SEL>
__device__ __forceinline__ void gemv16_body(
    const float* __restrict__ X, const float* __restrict__ W,
    const float* __restrict__ bias, float* __restrict__ out, int cblk)
{
    int tid = threadIdx.x, lane = tid & 31, w = tid >> 5;
    int c0 = cblk * 16 + w * 4;

    __shared__ float sX[B][1024];
    float acc[4][B];
#pragma unroll
    for (int j = 0; j < 4; j++)
#pragma unroll
        for (int b = 0; b < B; b++) acc[j][b] = 0.f;

#pragma unroll
    for (int p = 0; p < 2; p++) {
        __syncthreads();
        for (int i = tid; i < B * 256; i += 128) {
            int b = i >> 8, j = i & 255;
            ((float4*)sX[b])[j] = ((const float4*)(X + (size_t)b * D + p * 1024))[j];
        }
        __syncthreads();
#pragma unroll
        for (int kk = 0; kk < 1024; kk += 128) {
            int k = kk + lane * 4;
            float4 w4[4];
#pragma unroll
            for (int j = 0; j < 4; j++)
                w4[j] = *(const float4*)(W + (size_t)(c0 + j) * D + p * 1024 + k);
#pragma unroll
            for (int b = 0; b < B; b++) {
                float4 x4 = *(const float4*)(&sX[b][k]);
#pragma unroll
                for (int j = 0; j < 4; j++)
                    acc[j][b] += w4[j].x*x4.x + w4[j].y*x4.y + w4[j].z*x4.z + w4[j].w*x4.w;
            }
        }
    }

#pragma unroll
    for (int j = 0; j < 4; j++)
#pragma unroll
        for (int b = 0; b < B; b++) {
            float s = warp_sum(acc[j][b]);
            if (lane == j * 8 + b)
                out[(size_t)b * D + c0 + j] = s + bias[c0 + j];
        }
}

__global__ void __launch_bounds__(128) qkv_kernel(
    const float* __restrict__ X,
    const float* __restrict__ Wq, const float* __restrict__ bq,
    const float* __restrict__ Wk, const float* __restrict__ bk,
    const float* __restrict__ Wv, const float* __restrict__ bv)
{
    int which = blockIdx.x >> 7;
    int cblk  = blockIdx.x & 127;
    const float* W    = (which == 0) ? Wq : (which == 1) ? Wk : Wv;
    const float* bias = (which == 0) ? bq : (which == 1) ? bk : bv;
    float* out        = (which == 0) ? g_q : (which == 1) ? g_k : g_v;
    gemv16_body<0>(X, W, bias, out, cblk);
}

__global__ void __launch_bounds__(128) oproj_kernel(
    const float* __restrict__ W, const float* __restrict__ bias,
    float* __restrict__ out)
{
    gemv16_body<1>(g_o, W, bias, out, blockIdx.x);
}

// ---------------- RoPE on q and k (fp32 fast path) ----------------
__global__ void rope_qk(const int* __restrict__ hist) {
    int bh = blockIdx.x;
    int b  = bh >> 4;
    int d  = threadIdx.x;       // 0..63
    int pos = hist[b];
    float inv = exp2f((float)d * -0.2076205059304601f);
    float f   = (float)pos * inv;
    float sf, cf;
    sincosf(f, &sf, &cf);
    int base = bh * HD;
    {
        float x1 = g_q[base + d], x2 = g_q[base + d + 64];
        g_q[base + d]      = x1*cf - x2*sf;
        g_q[base + d + 64] = x2*cf + x1*sf;
    }
    {
        float x1 = g_k[base + d], x2 = g_k[base + d + 64];
        g_k[base + d]      = x1*cf - x2*sf;
        g_k[base + d + 64] = x2*cf + x1*sf;
    }
}

// ---------------- split-KV attention partial (pipelined; chunk-range arg) ----
__global__ void __launch_bounds__(128) attn_partial(
    const float* __restrict__ kc, const float* __restrict__ vc,
    const int* __restrict__ hist, const int* __restrict__ bofs, int cbase)
{
    int c = cbase + blockIdx.x, h = blockIdx.y, b = blockIdx.z;
    int pos = hist[b];
    int L = pos + 1;
    int s0 = c * CHUNK;
    int idx = (b*H + h)*NCHUNK + c;
    int tid = threadIdx.x, lane = tid & 31, w = tid >> 5;

    if (s0 >= L) {
        if (tid == 0) { g_pm[idx] = -1e30f; g_pl[idx] = 0.f; }
        return;
    }
    int s1 = min(s0 + CHUNK, L);

    __shared__ int sblk[MB];
    if (tid < MB) sblk[tid] = bofs[b*MB + tid];
    __syncthreads();

    const float* qp   = g_q + (size_t)b*D + h*HD;
    const float* knew = g_k + (size_t)b*D + h*HD;
    const float* vnew = g_v + (size_t)b*D + h*HD;

    float4 q4 = *(const float4*)(qp + lane*4);
    const float scale = 0.08838834764831845f;  // 1/sqrt(128)

    float m = -1e30f, lacc = 0.f;
    float4 oa = make_float4(0.f, 0.f, 0.f, 0.f);

    int base = s0 + w*4;

    float4 k4[4], v4[4];
#pragma unroll
    for (int i = 0; i < 4; i++) {
        int s = min(base + i, pos);
        const float *kr, *vr;
        if (s == pos) { kr = knew; vr = vnew; }
        else {
            size_t off = (((size_t)sblk[s >> 6]*BS + (s & 63))*H + h)*(size_t)HD;
            kr = kc + off; vr = vc + off;
        }
        k4[i] = *(const float4*)(kr + lane*4);
        v4[i] = *(const float4*)(vr + lane*4);
    }

    for (; base < s1; base += 16) {
        // ---- issue next iteration's loads first ----
        int nbase = base + 16;
        int pbase = (nbase < s1) ? nbase : base;
        float4 kn[4], vn[4];
#pragma unroll
        for (int i = 0; i < 4; i++) {
            int s = min(pbase + i, pos);
            const float *kr, *vr;
            if (s == pos) { kr = knew; vr = vnew; }
            else {
                size_t off = (((size_t)sblk[s >> 6]*BS + (s & 63))*H + h)*(size_t)HD;
                kr = kc + off; vr = vc + off;
            }
            kn[i] = *(const float4*)(kr + lane*4);
            vn[i] = *(const float4*)(vr + lane*4);
        }

        // ---- process current 4 keys ----
        float sc[4];
#pragma unroll
        for (int i = 0; i < 4; i++) {
            float dv = q4.x*k4[i].x + q4.y*k4[i].y + q4.z*k4[i].z + q4.w*k4[i].w;
            sc[i] = warp_sum(dv) * scale;
            if (base + i >= s1) sc[i] = -1e30f;
        }
        float mx = fmaxf(fmaxf(sc[0], sc[1]), fmaxf(sc[2], sc[3]));
        float mn = fmaxf(m, mx);
        float corr = __expf(m - mn);
        lacc *= corr;
        oa.x *= corr; oa.y *= corr; oa.z *= corr; oa.w *= corr;
#pragma unroll
        for (int i = 0; i < 4; i++) {
            float p = __expf(sc[i] - mn);
            lacc += p;
            oa.x += p * v4[i].x;
            oa.y += p * v4[i].y;
            oa.z += p * v4[i].z;
            oa.w += p * v4[i].w;
        }
        m = mn;

#pragma unroll
        for (int i = 0; i < 4; i++) { k4[i] = kn[i]; v4[i] = vn[i]; }
    }

    // merge the 4 warps
    __shared__ float sm_m[4], sm_l[4];
    __shared__ float sm_o[4][HD];
    if (lane == 0) { sm_m[w] = m; sm_l[w] = lacc; }
    *(float4*)&sm_o[w][lane*4] = oa;
    __syncthreads();

    float M = fmaxf(fmaxf(sm_m[0], sm_m[1]), fmaxf(sm_m[2], sm_m[3]));
    float f0 = (sm_l[0] > 0.f) ? __expf(sm_m[0] - M) : 0.f;
    float f1 = (sm_l[1] > 0.f) ? __expf(sm_m[1] - M) : 0.f;
    float f2 = (sm_l[2] > 0.f) ? __expf(sm_m[2] - M) : 0.f;
    float f3 = (sm_l[3] > 0.f) ? __expf(sm_m[3] - M) : 0.f;

    int d = tid;
    float acc = sm_o[0][d]*f0 + sm_o[1][d]*f1 + sm_o[2][d]*f2 + sm_o[3][d]*f3;
    g_po[(size_t)idx*HD + d] = acc;
    if (tid == 0) {
        g_pm[idx] = M;
        g_pl[idx] = sm_l[0]*f0 + sm_l[1]*f1 + sm_l[2]*f2 + sm_l[3]*f3;
    }
}

// ---------------- combine split-KV partials (4 warps: 4 chunks each) --------
__global__ void __launch_bounds__(128) attn_combine() {
    int bh = blockIdx.x;                // b*H + h
    int tid = threadIdx.x, lane = tid & 31, w = tid >> 5;

    // global max over 16 chunks (cheap broadcast reads)
    float M = -1e30f;
#pragma unroll
    for (int c = 0; c < NCHUNK; c++) M = fmaxf(M, g_pm[bh*NCHUNK + c]);

    // warp w accumulates chunks 4w..4w+3; lane owns dims lane*4..lane*4+3
    float Ls = 0.f;
    float4 acc = make_float4(0.f, 0.f, 0.f, 0.f);
#pragma unroll
    for (int j = 0; j < 4; j++) {
        int c = w * 4 + j;
        float lc = g_pl[bh*NCHUNK + c];
        float f = (lc > 0.f) ? __expf(g_pm[bh*NCHUNK + c] - M) : 0.f;
        Ls += lc * f;
        float4 p4 = *(const float4*)(g_po + (size_t)(bh*NCHUNK + c)*HD + lane*4);
        acc.x += p4.x * f;
        acc.y += p4.y * f;
        acc.z += p4.z * f;
        acc.w += p4.w * f;
    }

    __shared__ float sm_ls[4];
    __shared__ float sm_acc[4][HD];
    if (lane == 0) sm_ls[w] = Ls;
    *(float4*)&sm_acc[w][lane*4] = acc;
    __syncthreads();

    if (w == 0) {
        float Lt = sm_ls[0] + sm_ls[1] + sm_ls[2] + sm_ls[3];
        float inv = 1.f / Lt;
#pragma unroll
        for (int j = 0; j < 4; j++) {
            int d4 = lane*4;
            // sum the 4 warps' partials for this dim group (do once: j==0..3 covers dims via lane)
        }
        float4 a0 = *(const float4*)&sm_acc[0][lane*4];
        float4 a1 = *(const float4*)&sm_acc[1][lane*4];
        float4 a2 = *(const float4*)&sm_acc[2][lane*4];
        float4 a3 = *(const float4*)&sm_acc[3][lane*4];
        float4 r;
        r.x = (a0.x + a1.x + a2.x + a3.x) * inv;
        r.y = (a0.y + a1.y + a2.y + a3.y) * inv;
        r.z = (a0.z + a1.z + a2.z + a3.z) * inv;
        r.w = (a0.w + a1.w + a2.w + a3.w) * inv;
        *(float4*)(g_o + (size_t)bh*HD + lane*4) = r;
    }
}

// ---------------- entry point ----------------
extern "C" void kernel_launch(void* const* d_in, const int* in_sizes, int n_in,
                              void* d_out, int out_size) {
    const float* hs   = (const float*)d_in[0];
    const float* kc   = (const float*)d_in[1];
    const float* vc   = (const float*)d_in[2];
    const float* Wq   = (const float*)d_in[3];
    const float* bq   = (const float*)d_in[4];
    const float* Wk   = (const float*)d_in[5];
    const float* bk   = (const float*)d_in[6];
    const float* Wv   = (const float*)d_in[7];
    const float* bv   = (const float*)d_in[8];
    const float* Wo   = (const float*)d_in[9];
    const float* bo   = (const float*)d_in[10];
    const int*   hist = (const int*)d_in[11];
    const int*   bofs = (const int*)d_in[12];
    float* out = (float*)d_out;

    // Launch order chosen so ncu's profiled slot (index 3) lands on the LIVE
    // half of attn_partial (chunks 0-7; chunks 8-15 mostly exit immediately).
    qkv_kernel<<<3*128, 128>>>(hs, Wq, bq, Wk, bk, Wv, bv);                  // 0
    rope_qk<<<B*H, 64>>>(hist);                                              // 1
    attn_partial<<<dim3(NCHUNK/2, H, B), 128>>>(kc, vc, hist, bofs, 8);      // 2
    attn_partial<<<dim3(NCHUNK/2, H, B), 128>>>(kc, vc, hist, bofs, 0);      // 3 <- profiled
    attn_combine<<<B*H, 128>>>();                                            // 4
    oproj_kernel<<<128, 128>>>(Wo, bo, out);                                 // 5
}

// round 7
// speedup vs baseline: 1.0057x; 1.0057x over previous
#include <cuda_runtime.h>
#include <math.h>
#include <stdint.h>

#define B   8
#define H   16
#define HD  128
#define D   2048
#define NB  512
#define BS  64
#define MB  64
#define KV  (MB*BS)        // 4096
#define NCHUNK 16
#define CHUNK  (KV/NCHUNK) // 256

// ---------------- scratch (no allocations allowed) ----------------
__device__ float g_q[B*D];
__device__ float g_k[B*D];
__device__ float g_v[B*D];
__device__ float g_o[B*D];
__device__ float g_pm[B*H*NCHUNK];
__device__ float g_pl[B*H*NCHUNK];
__device__ float g_po[B*H*NCHUNK*HD];

__device__ __forceinline__ float warp_sum(float v) {
#pragma unroll
    for (int o = 16; o; o >>= 1) v += __shfl_xor_sync(0xffffffffu, v, o);
    return v;
}

// ---------------- GEMV v2: 16 cols/block, 8 warps, 2 cols/warp --------------
// All 16 W LDG.128 per pass are issued before any FMA consumes them
// (MLP=16/thread). X staged in smem (32KB halves), read via LDS.128.
__device__ __forceinline__ void gemv16w8_body(
    const float* __restrict__ X, const float* __restrict__ W,
    const float* __restrict__ bias, float* __restrict__ out, int cblk)
{
    int tid = threadIdx.x, lane = tid & 31, w = tid >> 5;
    int c0 = cblk * 16 + w * 2;         // warp's two columns: c0, c0+1

    __shared__ float sX[B][1024];
    float acc[2][B];
#pragma unroll
    for (int c = 0; c < 2; c++)
#pragma unroll
        for (int b = 0; b < B; b++) acc[c][b] = 0.f;

#pragma unroll
    for (int p = 0; p < 2; p++) {
        __syncthreads();
        for (int i = tid; i < B * 256; i += 256) {
            int b = i >> 8, j = i & 255;
            ((float4*)sX[b])[j] = ((const float4*)(X + (size_t)b * D + p * 1024))[j];
        }
        __syncthreads();

        // ---- 16 independent W loads up-front ----
        float4 wr[2][8];
#pragma unroll
        for (int kk = 0; kk < 8; kk++)
#pragma unroll
            for (int c = 0; c < 2; c++)
                wr[c][kk] = *(const float4*)(W + (size_t)(c0 + c) * D + p * 1024 + kk * 128 + lane * 4);

        // ---- consume against smem X ----
#pragma unroll
        for (int kk = 0; kk < 8; kk++) {
#pragma unroll
            for (int b = 0; b < B; b++) {
                float4 x4 = *(const float4*)(&sX[b][kk * 128 + lane * 4]);
                acc[0][b] += wr[0][kk].x*x4.x + wr[0][kk].y*x4.y + wr[0][kk].z*x4.z + wr[0][kk].w*x4.w;
                acc[1][b] += wr[1][kk].x*x4.x + wr[1][kk].y*x4.y + wr[1][kk].z*x4.z + wr[1][kk].w*x4.w;
            }
        }
    }

#pragma unroll
    for (int c = 0; c < 2; c++)
#pragma unroll
        for (int b = 0; b < B; b++) {
            float s = warp_sum(acc[c][b]);
            if (lane == c * 8 + b)
                out[(size_t)b * D + c0 + c] = s + bias[c0 + c];
        }
}

// Fused QKV: 3 * 128 = 384 blocks of 256 threads.
__global__ void __launch_bounds__(256) qkv_kernel(
    const float* __restrict__ X,
    const float* __restrict__ Wq, const float* __restrict__ bq,
    const float* __restrict__ Wk, const float* __restrict__ bk,
    const float* __restrict__ Wv, const float* __restrict__ bv)
{
    int which = blockIdx.x >> 7;
    int cblk  = blockIdx.x & 127;
    const float* W    = (which == 0) ? Wq : (which == 1) ? Wk : Wv;
    const float* bias = (which == 0) ? bq : (which == 1) ? bk : bv;
    float* out        = (which == 0) ? g_q : (which == 1) ? g_k : g_v;
    gemv16w8_body(X, W, bias, out, cblk);
}

__global__ void __launch_bounds__(256) oproj_kernel(
    const float* __restrict__ W, const float* __restrict__ bias,
    float* __restrict__ out)
{
    gemv16w8_body(g_o, W, bias, out, blockIdx.x);
}

// ---------------- RoPE on q and k (fp32 fast path) ----------------
__global__ void rope_qk(const int* __restrict__ hist) {
    int bh = blockIdx.x;
    int b  = bh >> 4;
    int d  = threadIdx.x;       // 0..63
    int pos = hist[b];
    float inv = exp2f((float)d * -0.2076205059304601f);
    float f   = (float)pos * inv;
    float sf, cf;
    sincosf(f, &sf, &cf);
    int base = bh * HD;
    {
        float x1 = g_q[base + d], x2 = g_q[base + d + 64];
        g_q[base + d]      = x1*cf - x2*sf;
        g_q[base + d + 64] = x2*cf + x1*sf;
    }
    {
        float x1 = g_k[base + d], x2 = g_k[base + d + 64];
        g_k[base + d]      = x1*cf - x2*sf;
        g_k[base + d + 64] = x2*cf + x1*sf;
    }
}

// ---------------- split-KV attention partial (R5 proven mainloop) -----------
__global__ void __launch_bounds__(128) attn_partial(
    const float* __restrict__ kc, const float* __restrict__ vc,
    const int* __restrict__ hist, const int* __restrict__ bofs)
{
    int c = blockIdx.x, h = blockIdx.y, b = blockIdx.z;
    int pos = hist[b];
    int L = pos + 1;
    int s0 = c * CHUNK;
    int idx = (b*H + h)*NCHUNK + c;
    int tid = threadIdx.x, lane = tid & 31, w = tid >> 5;

    if (s0 >= L) {
        if (tid == 0) { g_pm[idx] = -1e30f; g_pl[idx] = 0.f; }
        return;
    }
    int s1 = min(s0 + CHUNK, L);

    __shared__ int sblk[MB];
    if (tid < MB) sblk[tid] = bofs[b*MB + tid];
    __syncthreads();

    const float* qp   = g_q + (size_t)b*D + h*HD;
    const float* knew = g_k + (size_t)b*D + h*HD;
    const float* vnew = g_v + (size_t)b*D + h*HD;

    float4 q4 = *(const float4*)(qp + lane*4);
    const float scale = 0.08838834764831845f;  // 1/sqrt(128)

    float m = -1e30f, lacc = 0.f;
    float4 oa = make_float4(0.f, 0.f, 0.f, 0.f);

    int base = s0 + w*4;

    float4 k4[4], v4[4];
#pragma unroll
    for (int i = 0; i < 4; i++) {
        int s = min(base + i, pos);
        const float *kr, *vr;
        if (s == pos) { kr = knew; vr = vnew; }
        else {
            size_t off = (((size_t)sblk[s >> 6]*BS + (s & 63))*H + h)*(size_t)HD;
            kr = kc + off; vr = vc + off;
        }
        k4[i] = *(const float4*)(kr + lane*4);
        v4[i] = *(const float4*)(vr + lane*4);
    }

    for (; base < s1; base += 16) {
        int nbase = base + 16;
        int pbase = (nbase < s1) ? nbase : base;
        float4 kn[4], vn[4];
#pragma unroll
        for (int i = 0; i < 4; i++) {
            int s = min(pbase + i, pos);
            const float *kr, *vr;
            if (s == pos) { kr = knew; vr = vnew; }
            else {
                size_t off = (((size_t)sblk[s >> 6]*BS + (s & 63))*H + h)*(size_t)HD;
                kr = kc + off; vr = vc + off;
            }
            kn[i] = *(const float4*)(kr + lane*4);
            vn[i] = *(const float4*)(vr + lane*4);
        }

        float sc[4];
#pragma unroll
        for (int i = 0; i < 4; i++) {
            float dv = q4.x*k4[i].x + q4.y*k4[i].y + q4.z*k4[i].z + q4.w*k4[i].w;
            sc[i] = warp_sum(dv) * scale;
            if (base + i >= s1) sc[i] = -1e30f;
        }
        float mx = fmaxf(fmaxf(sc[0], sc[1]), fmaxf(sc[2], sc[3]));
        float mn = fmaxf(m, mx);
        float corr = __expf(m - mn);
        lacc *= corr;
        oa.x *= corr; oa.y *= corr; oa.z *= corr; oa.w *= corr;
#pragma unroll
        for (int i = 0; i < 4; i++) {
            float p = __expf(sc[i] - mn);
            lacc += p;
            oa.x += p * v4[i].x;
            oa.y += p * v4[i].y;
            oa.z += p * v4[i].z;
            oa.w += p * v4[i].w;
        }
        m = mn;

#pragma unroll
        for (int i = 0; i < 4; i++) { k4[i] = kn[i]; v4[i] = vn[i]; }
    }

    __shared__ float sm_m[4], sm_l[4];
    __shared__ float sm_o[4][HD];
    if (lane == 0) { sm_m[w] = m; sm_l[w] = lacc; }
    *(float4*)&sm_o[w][lane*4] = oa;
    __syncthreads();

    float M = fmaxf(fmaxf(sm_m[0], sm_m[1]), fmaxf(sm_m[2], sm_m[3]));
    float f0 = (sm_l[0] > 0.f) ? __expf(sm_m[0] - M) : 0.f;
    float f1 = (sm_l[1] > 0.f) ? __expf(sm_m[1] - M) : 0.f;
    float f2 = (sm_l[2] > 0.f) ? __expf(sm_m[2] - M) : 0.f;
    float f3 = (sm_l[3] > 0.f) ? __expf(sm_m[3] - M) : 0.f;

    int d = tid;
    float acc = sm_o[0][d]*f0 + sm_o[1][d]*f1 + sm_o[2][d]*f2 + sm_o[3][d]*f3;
    g_po[(size_t)idx*HD + d] = acc;
    if (tid == 0) {
        g_pm[idx] = M;
        g_pl[idx] = sm_l[0]*f0 + sm_l[1]*f1 + sm_l[2]*f2 + sm_l[3]*f3;
    }
}

// ---------------- combine split-KV partials (4 warps: 4 chunks each) --------
__global__ void __launch_bounds__(128) attn_combine() {
    int bh = blockIdx.x;
    int tid = threadIdx.x, lane = tid & 31, w = tid >> 5;

    float M = -1e30f;
#pragma unroll
    for (int c = 0; c < NCHUNK; c++) M = fmaxf(M, g_pm[bh*NCHUNK + c]);

    float Ls = 0.f;
    float4 acc = make_float4(0.f, 0.f, 0.f, 0.f);
#pragma unroll
    for (int j = 0; j < 4; j++) {
        int c = w * 4 + j;
        float lc = g_pl[bh*NCHUNK + c];
        float f = (lc > 0.f) ? __expf(g_pm[bh*NCHUNK + c] - M) : 0.f;
        Ls += lc * f;
        float4 p4 = *(const float4*)(g_po + (size_t)(bh*NCHUNK + c)*HD + lane*4);
        acc.x += p4.x * f;
        acc.y += p4.y * f;
        acc.z += p4.z * f;
        acc.w += p4.w * f;
    }

    __shared__ float sm_ls[4];
    __shared__ float sm_acc[4][HD];
    if (lane == 0) sm_ls[w] = Ls;
    *(float4*)&sm_acc[w][lane*4] = acc;
    __syncthreads();

    if (w == 0) {
        float Lt = sm_ls[0] + sm_ls[1] + sm_ls[2] + sm_ls[3];
        float inv = 1.f / Lt;
        float4 a0 = *(const float4*)&sm_acc[0][lane*4];
        float4 a1 = *(const float4*)&sm_acc[1][lane*4];
        float4 a2 = *(const float4*)&sm_acc[2][lane*4];
        float4 a3 = *(const float4*)&sm_acc[3][lane*4];
        float4 r;
        r.x = (a0.x + a1.x + a2.x + a3.x) * inv;
        r.y = (a0.y + a1.y + a2.y + a3.y) * inv;
        r.z = (a0.z + a1.z + a2.z + a3.z) * inv;
        r.w = (a0.w + a1.w + a2.w + a3.w) * inv;
        *(float4*)(g_o + (size_t)bh*HD + lane*4) = r;
    }
}

// ---------------- entry point ----------------
extern "C" void kernel_launch(void* const* d_in, const int* in_sizes, int n_in,
                              void* d_out, int out_size) {
    const float* hs   = (const float*)d_in[0];
    const float* kc   = (const float*)d_in[1];
    const float* vc   = (const float*)d_in[2];
    const float* Wq   = (const float*)d_in[3];
    const float* bq   = (const float*)d_in[4];
    const float* Wk   = (const float*)d_in[5];
    const float* bk   = (const float*)d_in[6];
    const float* Wv   = (const float*)d_in[7];
    const float* bv   = (const float*)d_in[8];
    const float* Wo   = (const float*)d_in[9];
    const float* bo   = (const float*)d_in[10];
    const int*   hist = (const int*)d_in[11];
    const int*   bofs = (const int*)d_in[12];
    float* out = (float*)d_out;

    qkv_kernel<<<3*128, 256>>>(hs, Wq, bq, Wk, bk, Wv, bv);
    rope_qk<<<B*H, 64>>>(hist);
    attn_partial<<<dim3(NCHUNK, H, B), 128>>>(kc, vc, hist, bofs);
    attn_combine<<<B*H, 128>>>();
    oproj_kernel<<<128, 256>>>(Wo, bo, out);
}